// round 1
// baseline (speedup 1.0000x reference)
#include <cuda_runtime.h>

#define NB 8
#define NS 2048
#define ND 20
#define NH 4
#define NDK 5

// Scratch (device globals — no allocation allowed)
__device__ int   g_cidx[NB][NS];
__device__ int   g_nk[NB];
__device__ float g_Q[3][NB][NH][NS][8];   // Q-projection (proj0), pre-scaled by log2e/sqrt(5)
__device__ float g_K[3][NB][NH][NS][8];   // K-projection (proj1), compacted over valid keys
__device__ float g_V[3][NB][NH][NS][8];   // V-projection (proj2), compacted over valid keys
__device__ float g_O[6][NB][NS][ND];      // per-pair attention outputs (h*5+d packed)

__constant__ int c_pa[6] = {0, 1, 0, 2, 1, 2};  // Q source per pair
__constant__ int c_pc[6] = {1, 0, 2, 0, 2, 1};  // K/V source per pair

// ---------------------------------------------------------------------------
// 1) Per-batch key compaction: mask[b][s]==1 -> compact index, else -1
// ---------------------------------------------------------------------------
__global__ void compact_kernel(const int* __restrict__ mask) {
    int b = blockIdx.x;
    int lane = threadIdx.x;  // 32 threads
    int count = 0;
    for (int s0 = 0; s0 < NS; s0 += 32) {
        int m = mask[b * NS + s0 + lane];
        unsigned bal = __ballot_sync(0xffffffffu, m != 0);
        int pos = count + __popc(bal & ((1u << lane) - 1u));
        g_cidx[b][s0 + lane] = m ? pos : -1;
        count += __popc(bal);
    }
    if (lane == 0) g_nk[b] = count;
}

// ---------------------------------------------------------------------------
// 2) All 9 projections (3 sources x {W0,W1,W2}); Q pre-scaled; K/V compacted
// ---------------------------------------------------------------------------
__global__ void proj_kernel(const float* __restrict__ xq,
                            const float* __restrict__ xk,
                            const float* __restrict__ xv,
                            const float* __restrict__ W0, const float* __restrict__ b0,
                            const float* __restrict__ W1, const float* __restrict__ b1,
                            const float* __restrict__ W2, const float* __restrict__ b2) {
    __shared__ float sW[3][ND * ND];
    __shared__ float sb[3][ND];
    for (int i = threadIdx.x; i < ND * ND; i += blockDim.x) {
        sW[0][i] = W0[i];
        sW[1][i] = W1[i];
        sW[2][i] = W2[i];
    }
    for (int i = threadIdx.x; i < ND; i += blockDim.x) {
        sb[0][i] = b0[i];
        sb[1][i] = b1[i];
        sb[2][i] = b2[i];
    }
    __syncthreads();

    int idx = blockIdx.x * blockDim.x + threadIdx.x;
    if (idx >= 3 * NB * NS) return;
    int src = idx / (NB * NS);
    int bs  = idx - src * (NB * NS);
    int b   = bs / NS;
    int s   = bs - b * NS;

    const float* x = (src == 0 ? xq : (src == 1 ? xk : xv)) + (size_t)bs * ND;
    float xr[ND];
#pragma unroll
    for (int i = 0; i < ND; i++) xr[i] = x[i];

    int cj = g_cidx[b][s];
    // fold 1/sqrt(DK) * log2(e) into Q so softmax = single ex2
    const float qsc = 1.44269504088896340736f * 0.44721359549995793928f;

#pragma unroll
    for (int o = 0; o < ND; o++) {
        float y0 = sb[0][o], y1 = sb[1][o], y2 = sb[2][o];
#pragma unroll
        for (int i = 0; i < ND; i++) {
            y0 = fmaf(xr[i], sW[0][o * ND + i], y0);
            y1 = fmaf(xr[i], sW[1][o * ND + i], y1);
            y2 = fmaf(xr[i], sW[2][o * ND + i], y2);
        }
        int h = o / NDK, d = o - h * NDK;
        g_Q[src][b][h][s][d] = y0 * qsc;
        if (cj >= 0) {
            g_K[src][b][h][cj][d] = y1;
            g_V[src][b][h][cj][d] = y2;
        }
    }
}

// ---------------------------------------------------------------------------
// 3) Attention: one block = (pair, b, h, qtile of 512). 128 thr x 4 queries.
//    Inner loop over compacted keys; K/V rows are uniform-address (warp
//    broadcast) vector loads, L1-resident. Unsafe softmax (single EX2).
// ---------------------------------------------------------------------------
__global__ void __launch_bounds__(128) attn_kernel() {
    int bi   = blockIdx.x;
    int pair = bi >> 7;
    int rem  = bi & 127;
    int b    = rem >> 4;
    int h    = (rem >> 2) & 3;
    int tile = rem & 3;
    int a = c_pa[pair], c = c_pc[pair];
    int nk = g_nk[b];

    const float* __restrict__ Kb = &g_K[c][b][h][0][0];
    const float* __restrict__ Vb = &g_V[c][b][h][0][0];
    int tid = threadIdx.x;

    float q0[4], q1[4], q2[4], q3[4], q4[4];
    float a0[4], a1[4], a2[4], a3[4], a4[4], l[4];
#pragma unroll
    for (int w = 0; w < 4; w++) {
        int q = tile * 512 + w * 128 + tid;
        const float* qp = &g_Q[a][b][h][q][0];
        float4 t = *reinterpret_cast<const float4*>(qp);
        q0[w] = t.x; q1[w] = t.y; q2[w] = t.z; q3[w] = t.w; q4[w] = qp[4];
        a0[w] = a1[w] = a2[w] = a3[w] = a4[w] = 0.f;
        l[w] = 0.f;
    }

    for (int j = 0; j < nk; j++) {
        const float* kp = Kb + j * 8;
        float4 kt = *reinterpret_cast<const float4*>(kp);
        float  k4 = kp[4];
        const float* vp = Vb + j * 8;
        float4 vt = *reinterpret_cast<const float4*>(vp);
        float  v4 = vp[4];
#pragma unroll
        for (int w = 0; w < 4; w++) {
            float s = fmaf(q0[w], kt.x,
                      fmaf(q1[w], kt.y,
                      fmaf(q2[w], kt.z,
                      fmaf(q3[w], kt.w, q4[w] * k4))));
            float p;
            asm("ex2.approx.ftz.f32 %0, %1;" : "=f"(p) : "f"(s));
            l[w] += p;
            a0[w] = fmaf(p, vt.x, a0[w]);
            a1[w] = fmaf(p, vt.y, a1[w]);
            a2[w] = fmaf(p, vt.z, a2[w]);
            a3[w] = fmaf(p, vt.w, a3[w]);
            a4[w] = fmaf(p, v4,  a4[w]);
        }
    }

#pragma unroll
    for (int w = 0; w < 4; w++) {
        int q = tile * 512 + w * 128 + tid;
        float inv = 1.0f / l[w];
        float* op = &g_O[pair][b][q][h * NDK];
        op[0] = a0[w] * inv;
        op[1] = a1[w] * inv;
        op[2] = a2[w] * inv;
        op[3] = a3[w] * inv;
        op[4] = a4[w] * inv;
    }
}

// ---------------------------------------------------------------------------
// 4) Sum 6 pair outputs + output projection W3/b3
// ---------------------------------------------------------------------------
__global__ void outproj_kernel(const float* __restrict__ W3,
                               const float* __restrict__ b3,
                               float* __restrict__ out) {
    __shared__ float sW[ND * ND];
    __shared__ float sb[ND];
    for (int i = threadIdx.x; i < ND * ND; i += blockDim.x) sW[i] = W3[i];
    for (int i = threadIdx.x; i < ND; i += blockDim.x) sb[i] = b3[i];
    __syncthreads();

    int bs = blockIdx.x * blockDim.x + threadIdx.x;
    if (bs >= NB * NS) return;

    const float* Ob = &g_O[0][0][0][0];
    float x[ND];
#pragma unroll
    for (int i = 0; i < ND; i++) {
        float t = 0.f;
#pragma unroll
        for (int p = 0; p < 6; p++)
            t += Ob[((size_t)p * NB * NS + bs) * ND + i];
        x[i] = t;
    }
    float* op = out + (size_t)bs * ND;
#pragma unroll
    for (int o = 0; o < ND; o++) {
        float y = sb[o];
#pragma unroll
        for (int i = 0; i < ND; i++) y = fmaf(x[i], sW[o * ND + i], y);
        op[o] = y;
    }
}

// ---------------------------------------------------------------------------
extern "C" void kernel_launch(void* const* d_in, const int* in_sizes, int n_in,
                              void* d_out, int out_size) {
    const float* q   = (const float*)d_in[0];
    const float* k   = (const float*)d_in[1];
    const float* v   = (const float*)d_in[2];
    const int*   msk = (const int*)d_in[3];
    const float* W0  = (const float*)d_in[4];
    const float* b0  = (const float*)d_in[5];
    const float* W1  = (const float*)d_in[6];
    const float* b1  = (const float*)d_in[7];
    const float* W2  = (const float*)d_in[8];
    const float* b2  = (const float*)d_in[9];
    const float* W3  = (const float*)d_in[10];
    const float* b3  = (const float*)d_in[11];
    float* out = (float*)d_out;

    compact_kernel<<<NB, 32>>>(msk);
    proj_kernel<<<(3 * NB * NS + 255) / 256, 256>>>(q, k, v, W0, b0, W1, b1, W2, b2);
    attn_kernel<<<6 * 128, 128>>>();
    outproj_kernel<<<(NB * NS + 127) / 128, 128>>>(W3, b3, out);
}

// round 2
// speedup vs baseline: 1.2164x; 1.2164x over previous
#include <cuda_runtime.h>

#define NB 8
#define NS 2048
#define ND 20
#define NH 4
#define NDK 5

// ---- packed f32x2 helpers (B300 2-wide FMA pipe) ---------------------------
#define FMA2(d, a, b, c) asm("fma.rn.f32x2 %0, %1, %2, %3;" : "=l"(d) : "l"(a), "l"(b), "l"(c))
#define MUL2(d, a, b)    asm("mul.rn.f32x2 %0, %1, %2;"     : "=l"(d) : "l"(a), "l"(b))
#define PACK2(d, lo, hi) asm("mov.b64 %0, {%1, %2};" : "=l"(d) : "r"(__float_as_uint(lo)), "r"(__float_as_uint(hi)))
#define UNPACK2(lo, hi, v) do { unsigned _ulo, _uhi; \
    asm("mov.b64 {%0, %1}, %2;" : "=r"(_ulo), "=r"(_uhi) : "l"(v)); \
    lo = __uint_as_float(_ulo); hi = __uint_as_float(_uhi); } while (0)

__device__ __forceinline__ float ex2f(float x) {
    float r; asm("ex2.approx.ftz.f32 %0, %1;" : "=f"(r) : "f"(x)); return r;
}

// Scratch (device globals — no allocation allowed)
__device__ int   g_cidx[NB][NS];
__device__ int   g_nk[NB];
__device__ float g_Q[3][NB][NH][NS][8];          // Q proj, pre-scaled by log2e/sqrt(5)
// KV record per compacted key-pair (t = cj>>1), 24 floats / 96 bytes:
//  [0..9]   KK: (k_j0[d], k_j1[d]) for d=0..4        (5 x f32x2)
//  [10..15] V_j0: (v0,v1),(v2,v3),(v4, 1.0)          (3 x f32x2; 1.0 merges l-sum)
//  [16..21] V_j1: (v0,v1),(v2,v3),(v4, 1.0)
//  [22..23] pad
__device__ float g_KV[3][NB][NH][NS / 2][24];
__device__ float g_O[6][NB][NS][ND];             // per-pair attention outputs

__constant__ int c_pa[6] = {0, 1, 0, 2, 1, 2};   // Q source per pair
__constant__ int c_pc[6] = {1, 0, 2, 0, 2, 1};   // K/V source per pair

// ---------------------------------------------------------------------------
// 1) Per-batch key compaction
// ---------------------------------------------------------------------------
__global__ void compact_kernel(const int* __restrict__ mask) {
    int b = blockIdx.x;
    int lane = threadIdx.x;  // 32 threads
    int count = 0;
    for (int s0 = 0; s0 < NS; s0 += 32) {
        int m = mask[b * NS + s0 + lane];
        unsigned bal = __ballot_sync(0xffffffffu, m != 0);
        int pos = count + __popc(bal & ((1u << lane) - 1u));
        g_cidx[b][s0 + lane] = m ? pos : -1;
        count += __popc(bal);
    }
    if (lane == 0) g_nk[b] = count;
}

// ---------------------------------------------------------------------------
// 2) All 9 projections; Q pre-scaled; K/V written into interleaved records
// ---------------------------------------------------------------------------
__global__ void proj_kernel(const float* __restrict__ xq,
                            const float* __restrict__ xk,
                            const float* __restrict__ xv,
                            const float* __restrict__ W0, const float* __restrict__ b0,
                            const float* __restrict__ W1, const float* __restrict__ b1,
                            const float* __restrict__ W2, const float* __restrict__ b2) {
    __shared__ float sW[3][ND * ND];
    __shared__ float sb[3][ND];
    for (int i = threadIdx.x; i < ND * ND; i += blockDim.x) {
        sW[0][i] = W0[i]; sW[1][i] = W1[i]; sW[2][i] = W2[i];
    }
    for (int i = threadIdx.x; i < ND; i += blockDim.x) {
        sb[0][i] = b0[i]; sb[1][i] = b1[i]; sb[2][i] = b2[i];
    }
    __syncthreads();

    int idx = blockIdx.x * blockDim.x + threadIdx.x;
    if (idx >= 3 * NB * NS) return;
    int src = idx / (NB * NS);
    int bs  = idx - src * (NB * NS);
    int b   = bs / NS;
    int s   = bs - b * NS;

    const float* x = (src == 0 ? xq : (src == 1 ? xk : xv)) + (size_t)bs * ND;
    float xr[ND];
#pragma unroll
    for (int i = 0; i < ND; i++) xr[i] = x[i];

    int cj = g_cidx[b][s];
    int t = cj >> 1, lane = cj & 1;
    const float qsc = 1.44269504088896340736f * 0.44721359549995793928f;

#pragma unroll
    for (int o = 0; o < ND; o++) {
        float y0 = sb[0][o], y1 = sb[1][o], y2 = sb[2][o];
#pragma unroll
        for (int i = 0; i < ND; i++) {
            y0 = fmaf(xr[i], sW[0][o * ND + i], y0);
            y1 = fmaf(xr[i], sW[1][o * ND + i], y1);
            y2 = fmaf(xr[i], sW[2][o * ND + i], y2);
        }
        int h = o / NDK, d = o - h * NDK;
        g_Q[src][b][h][s][d] = y0 * qsc;
        if (cj >= 0) {
            float* rec = &g_KV[src][b][h][t][0];
            rec[2 * d + lane] = y1;                 // interleaved K
            rec[10 + lane * 6 + d] = y2;            // V
            if (d == 4) rec[10 + lane * 6 + 5] = 1.0f;  // l-sum constant
        }
    }
}

// ---------------------------------------------------------------------------
// 3) Attention: block = (pair, b, h, qtile of 512). 128 thr x 4 queries.
//    Inner loop over key PAIRS with packed f32x2 math (5.5 fma-ops/key).
// ---------------------------------------------------------------------------
__global__ void __launch_bounds__(128) attn_kernel() {
    int bi   = blockIdx.x;
    int pair = bi >> 7;
    int rem  = bi & 127;
    int b    = rem >> 4;
    int h    = (rem >> 2) & 3;
    int tile = rem & 3;
    int a = c_pa[pair], c = c_pc[pair];
    int nk = g_nk[b];
    int np = nk >> 1;

    const float* __restrict__ KVb = &g_KV[c][b][h][0][0];
    int tid = threadIdx.x;

    unsigned long long Q2[4][5];     // (q_d, q_d) duplicated packs
    unsigned long long A01[4], A23[4], A4L[4];
#pragma unroll
    for (int w = 0; w < 4; w++) {
        int q = tile * 512 + w * 128 + tid;
        const float* qp = &g_Q[a][b][h][q][0];
        float4 tq = *reinterpret_cast<const float4*>(qp);
        float q4 = qp[4];
        PACK2(Q2[w][0], tq.x, tq.x);
        PACK2(Q2[w][1], tq.y, tq.y);
        PACK2(Q2[w][2], tq.z, tq.z);
        PACK2(Q2[w][3], tq.w, tq.w);
        PACK2(Q2[w][4], q4, q4);
        A01[w] = 0ull; A23[w] = 0ull; A4L[w] = 0ull;
    }

    for (int t = 0; t < np; t++) {
        const ulonglong2* r = reinterpret_cast<const ulonglong2*>(KVb + t * 24);
        ulonglong2 L0 = r[0];   // KK0, KK1
        ulonglong2 L1 = r[1];   // KK2, KK3
        ulonglong2 L2 = r[2];   // KK4, V0_01
        ulonglong2 L3 = r[3];   // V0_23, V0_4c
        ulonglong2 L4 = r[4];   // V1_01, V1_23
        ulonglong2 L5 = r[5];   // V1_4c, pad
#pragma unroll
        for (int w = 0; w < 4; w++) {
            unsigned long long s2;
            MUL2(s2, Q2[w][0], L0.x);
            FMA2(s2, Q2[w][1], L0.y, s2);
            FMA2(s2, Q2[w][2], L1.x, s2);
            FMA2(s2, Q2[w][3], L1.y, s2);
            FMA2(s2, Q2[w][4], L2.x, s2);
            float s0, s1;
            UNPACK2(s0, s1, s2);
            float p0 = ex2f(s0);
            float p1 = ex2f(s1);
            unsigned long long p02, p12;
            PACK2(p02, p0, p0);
            PACK2(p12, p1, p1);
            FMA2(A01[w], p02, L2.y, A01[w]);
            FMA2(A23[w], p02, L3.x, A23[w]);
            FMA2(A4L[w], p02, L3.y, A4L[w]);
            FMA2(A01[w], p12, L4.x, A01[w]);
            FMA2(A23[w], p12, L4.y, A23[w]);
            FMA2(A4L[w], p12, L5.x, A4L[w]);
        }
    }

    // unpack accumulators; handle odd tail key scalar; write
    const float* tr = KVb + (size_t)np * 24;   // tail record (lane 0 only valid)
    bool odd = (nk & 1) != 0;
#pragma unroll
    for (int w = 0; w < 4; w++) {
        float a0, a1, a2, a3, a4, l;
        UNPACK2(a0, a1, A01[w]);
        UNPACK2(a2, a3, A23[w]);
        UNPACK2(a4, l,  A4L[w]);
        if (odd) {
            float q0, qq; UNPACK2(q0, qq, Q2[w][0]);
            float q1; UNPACK2(q1, qq, Q2[w][1]);
            float q2; UNPACK2(q2, qq, Q2[w][2]);
            float q3; UNPACK2(q3, qq, Q2[w][3]);
            float q4; UNPACK2(q4, qq, Q2[w][4]);
            float s = fmaf(q0, tr[0], fmaf(q1, tr[2], fmaf(q2, tr[4],
                      fmaf(q3, tr[6], q4 * tr[8]))));
            float p = ex2f(s);
            l  += p;
            a0 = fmaf(p, tr[10], a0);
            a1 = fmaf(p, tr[11], a1);
            a2 = fmaf(p, tr[12], a2);
            a3 = fmaf(p, tr[13], a3);
            a4 = fmaf(p, tr[14], a4);
        }
        int q = tile * 512 + w * 128 + tid;
        float inv = 1.0f / l;
        float* op = &g_O[pair][b][q][h * NDK];
        op[0] = a0 * inv;
        op[1] = a1 * inv;
        op[2] = a2 * inv;
        op[3] = a3 * inv;
        op[4] = a4 * inv;
    }
}

// ---------------------------------------------------------------------------
// 4) Sum 6 pair outputs + output projection W3/b3
// ---------------------------------------------------------------------------
__global__ void outproj_kernel(const float* __restrict__ W3,
                               const float* __restrict__ b3,
                               float* __restrict__ out) {
    __shared__ float sW[ND * ND];
    __shared__ float sb[ND];
    for (int i = threadIdx.x; i < ND * ND; i += blockDim.x) sW[i] = W3[i];
    for (int i = threadIdx.x; i < ND; i += blockDim.x) sb[i] = b3[i];
    __syncthreads();

    int bs = blockIdx.x * blockDim.x + threadIdx.x;
    if (bs >= NB * NS) return;

    const float* Ob = &g_O[0][0][0][0];
    float x[ND];
#pragma unroll
    for (int i = 0; i < ND; i++) {
        float t = 0.f;
#pragma unroll
        for (int p = 0; p < 6; p++)
            t += Ob[((size_t)p * NB * NS + bs) * ND + i];
        x[i] = t;
    }
    float* op = out + (size_t)bs * ND;
#pragma unroll
    for (int o = 0; o < ND; o++) {
        float y = sb[o];
#pragma unroll
        for (int i = 0; i < ND; i++) y = fmaf(x[i], sW[o * ND + i], y);
        op[o] = y;
    }
}

// ---------------------------------------------------------------------------
extern "C" void kernel_launch(void* const* d_in, const int* in_sizes, int n_in,
                              void* d_out, int out_size) {
    const float* q   = (const float*)d_in[0];
    const float* k   = (const float*)d_in[1];
    const float* v   = (const float*)d_in[2];
    const int*   msk = (const int*)d_in[3];
    const float* W0  = (const float*)d_in[4];
    const float* b0  = (const float*)d_in[5];
    const float* W1  = (const float*)d_in[6];
    const float* b1  = (const float*)d_in[7];
    const float* W2  = (const float*)d_in[8];
    const float* b2  = (const float*)d_in[9];
    const float* W3  = (const float*)d_in[10];
    const float* b3  = (const float*)d_in[11];
    float* out = (float*)d_out;

    compact_kernel<<<NB, 32>>>(msk);
    proj_kernel<<<(3 * NB * NS + 255) / 256, 256>>>(q, k, v, W0, b0, W1, b1, W2, b2);
    attn_kernel<<<6 * 128, 128>>>();
    outproj_kernel<<<(NB * NS + 127) / 128, 128>>>(W3, b3, out);
}

// round 3
// speedup vs baseline: 1.2941x; 1.0638x over previous
#include <cuda_runtime.h>

#define NB 8
#define NS 2048
#define ND 20
#define NH 4
#define NDK 5
#define FULLM 0xffffffffu

__device__ __forceinline__ float ex2f(float x) {
    float r; asm("ex2.approx.ftz.f32 %0, %1;" : "=f"(r) : "f"(x)); return r;
}
__device__ __forceinline__ float tf32r(float x) {
    unsigned u; asm("cvt.rna.tf32.f32 %0, %1;" : "=r"(u) : "f"(x));
    return __uint_as_float(u);
}

// Scratch (device globals)
__device__ int   g_cidx[NB][NS];
__device__ int   g_nk[NB];
// mma.m16n8k8 fragment planes:
// Qf[src][b][h][qtile][plane a0..a3][lane]   (A-frag of QK mma; k-dim padded 5->8)
// Kf[src][b][h][chunk][plane b0,b1][lane]    (B-frag of QK mma: n=key, k=dim)
// Vf[src][b][h][chunk][plane b0,b1][lane]    (B-frag of PV mma: k=key, n=dim; n=5 is ones col)
__device__ float g_Qf[3][NB][NH][128][4][32];
__device__ float g_Kf[3][NB][NH][256][2][32];
__device__ float g_Vf[3][NB][NH][256][2][32];
__device__ float g_O[6][NB][NS][ND];

__constant__ int c_pa[6] = {0, 1, 0, 2, 1, 2};   // Q source per pair
__constant__ int c_pc[6] = {1, 0, 2, 0, 2, 1};   // K/V source per pair

// ---------------------------------------------------------------------------
// 1) Per-batch key compaction
// ---------------------------------------------------------------------------
__global__ void compact_kernel(const int* __restrict__ mask) {
    int b = blockIdx.x;
    int lane = threadIdx.x;
    int count = 0;
    for (int s0 = 0; s0 < NS; s0 += 32) {
        int m = mask[b * NS + s0 + lane];
        unsigned bal = __ballot_sync(FULLM, m != 0);
        int pos = count + __popc(bal & ((1u << lane) - 1u));
        g_cidx[b][s0 + lane] = m ? pos : -1;
        count += __popc(bal);
    }
    if (lane == 0) g_nk[b] = count;
}

// ---------------------------------------------------------------------------
// 2a) Zero all fragment arrays (pads / unwritten slots must be 0)
// ---------------------------------------------------------------------------
__global__ void zero_kernel() {
    size_t n4 = (sizeof(g_Qf) + sizeof(g_Kf) + sizeof(g_Vf)) / 16;
    float4* q = reinterpret_cast<float4*>(&g_Qf[0][0][0][0][0][0]);
    // arrays are declared adjacent? NOT guaranteed — zero each separately.
    size_t nq = sizeof(g_Qf) / 16, nk = sizeof(g_Kf) / 16, nv = sizeof(g_Vf) / 16;
    float4 z = make_float4(0.f, 0.f, 0.f, 0.f);
    float4* kp = reinterpret_cast<float4*>(&g_Kf[0][0][0][0][0][0]);
    float4* vp = reinterpret_cast<float4*>(&g_Vf[0][0][0][0][0][0]);
    for (size_t i = blockIdx.x * blockDim.x + threadIdx.x; i < n4;
         i += (size_t)gridDim.x * blockDim.x) {
        if (i < nq) q[i] = z;
        else if (i < nq + nk) kp[i - nq] = z;
        else vp[i - nq - nk] = z;
    }
}

// 2b) Set the ones-column (n=5) of V fragments for valid keys only
__global__ void ones_kernel() {
    // idx over [3][NB][NH][256 chunks][8 rows]
    int idx = blockIdx.x * blockDim.x + threadIdx.x;
    if (idx >= 3 * NB * NH * 256 * 8) return;
    int r   = idx & 7;
    int ch  = (idx >> 3) & 255;
    int h   = (idx >> 11) & 3;
    int b   = (idx >> 13) & 7;
    int src = idx >> 16;
    if (ch * 8 + r < g_nk[b]) {
        int plane = r >> 2, t = r & 3;
        g_Vf[src][b][h][ch][plane][20 + t] = 1.0f;   // lane = n*4 + t, n = 5
    }
}

// ---------------------------------------------------------------------------
// 3) All 9 projections -> fragment layouts (Q prescaled by log2e/sqrt(5), rna-tf32)
// ---------------------------------------------------------------------------
__global__ void proj_kernel(const float* __restrict__ xq,
                            const float* __restrict__ xk,
                            const float* __restrict__ xv,
                            const float* __restrict__ W0, const float* __restrict__ b0,
                            const float* __restrict__ W1, const float* __restrict__ b1,
                            const float* __restrict__ W2, const float* __restrict__ b2) {
    __shared__ float sW[3][ND * ND];
    __shared__ float sb[3][ND];
    for (int i = threadIdx.x; i < ND * ND; i += blockDim.x) {
        sW[0][i] = W0[i]; sW[1][i] = W1[i]; sW[2][i] = W2[i];
    }
    for (int i = threadIdx.x; i < ND; i += blockDim.x) {
        sb[0][i] = b0[i]; sb[1][i] = b1[i]; sb[2][i] = b2[i];
    }
    __syncthreads();

    int idx = blockIdx.x * blockDim.x + threadIdx.x;
    if (idx >= 3 * NB * NS) return;
    int src = idx / (NB * NS);
    int bs  = idx - src * (NB * NS);
    int b   = bs / NS;
    int s   = bs - b * NS;

    const float* x = (src == 0 ? xq : (src == 1 ? xk : xv)) + (size_t)bs * ND;
    float xr[ND];
#pragma unroll
    for (int i = 0; i < ND; i++) xr[i] = x[i];

    int cj = g_cidx[b][s];
    int qt = s >> 4, r = s & 15;
    int qg = r & 7, half = r >> 3;
    int ch = cj >> 3;
    int kg = cj & 7;                       // Kf: key-in-chunk -> g
    int vslot = (cj & 7) >> 2, vt = cj & 3;  // Vf: key-in-chunk -> (plane, t)
    const float qsc = 1.44269504088896340736f * 0.44721359549995793928f;

#pragma unroll
    for (int o = 0; o < ND; o++) {
        float y0 = sb[0][o], y1 = sb[1][o], y2 = sb[2][o];
#pragma unroll
        for (int i = 0; i < ND; i++) {
            y0 = fmaf(xr[i], sW[0][o * ND + i], y0);
            y1 = fmaf(xr[i], sW[1][o * ND + i], y1);
            y2 = fmaf(xr[i], sW[2][o * ND + i], y2);
        }
        int h = o / NDK, d = o - h * NDK;
        y0 = tf32r(y0 * qsc);
        y1 = tf32r(y1);
        y2 = tf32r(y2);
        // Q fragment (A of mma1): d<4 -> plane half, lane qg*4+d ; d==4 -> plane 2+half, lane qg*4
        if (d < 4) g_Qf[src][b][h][qt][half][qg * 4 + d] = y0;
        else       g_Qf[src][b][h][qt][2 + half][qg * 4] = y0;
        if (cj >= 0) {
            // K fragment (B of mma1): n=key=kg, k=dim: d<4 -> plane0 lane kg*4+d ; d==4 -> plane1 lane kg*4
            if (d < 4) g_Kf[src][b][h][ch][0][kg * 4 + d] = y1;
            else       g_Kf[src][b][h][ch][1][kg * 4] = y1;
            // V fragment (B of mma2): k=key -> (vslot, vt), n=dim=d: lane d*4+vt
            g_Vf[src][b][h][ch][vslot][d * 4 + vt] = y2;
        }
    }
}

// ---------------------------------------------------------------------------
// 4) Attention: warp = 16-query tile, flash loop over 8-key chunks via mma.tf32
// ---------------------------------------------------------------------------
__global__ void __launch_bounds__(128) attn_kernel() {
    int bi = blockIdx.x;
    int pair = bi >> 10;
    int rem  = bi & 1023;
    int b    = rem >> 7;
    int rem2 = rem & 127;
    int h    = rem2 >> 5;
    int qt4  = rem2 & 31;
    int wid  = threadIdx.x >> 5;
    int lane = threadIdx.x & 31;
    int qt   = qt4 * 4 + wid;
    int a = c_pa[pair], c = c_pc[pair];
    int nc = (g_nk[b] + 7) >> 3;

    const float* Qb = &g_Qf[a][b][h][qt][0][0];
    unsigned ua0 = __float_as_uint(Qb[lane]);
    unsigned ua1 = __float_as_uint(Qb[32 + lane]);
    unsigned ua2 = __float_as_uint(Qb[64 + lane]);
    unsigned ua3 = __float_as_uint(Qb[96 + lane]);

    const float* Kc = &g_Kf[c][b][h][0][0][0];
    const float* Vc = &g_Vf[c][b][h][0][0][0];

    float o0 = 0.f, o1 = 0.f, o2 = 0.f, o3 = 0.f;
    const float zf = 0.f;
    int t = lane & 3;
    unsigned srcA = (lane & ~3u) | (unsigned)(t >> 1);
    unsigned srcB = srcA | 2u;
    bool odd = (t & 1) != 0;

    for (int ch = 0; ch < nc; ch++) {
        unsigned kb0 = __float_as_uint(Kc[ch * 64 + lane]);
        unsigned kb1 = __float_as_uint(Kc[ch * 64 + 32 + lane]);
        unsigned vb0 = __float_as_uint(Vc[ch * 64 + lane]);
        unsigned vb1 = __float_as_uint(Vc[ch * 64 + 32 + lane]);

        float s0, s1, s2, s3;
        asm volatile(
            "mma.sync.aligned.m16n8k8.row.col.f32.tf32.tf32.f32 "
            "{%0,%1,%2,%3}, {%4,%5,%6,%7}, {%8,%9}, {%10,%11,%12,%13};\n"
            : "=f"(s0), "=f"(s1), "=f"(s2), "=f"(s3)
            : "r"(ua0), "r"(ua1), "r"(ua2), "r"(ua3),
              "r"(kb0), "r"(kb1),
              "f"(zf), "f"(zf), "f"(zf), "f"(zf));

        float e0 = ex2f(s0), e1 = ex2f(s1), e2 = ex2f(s2), e3 = ex2f(s3);

        float x0 = __shfl_sync(FULLM, e0, srcA);
        float x1 = __shfl_sync(FULLM, e1, srcA);
        float y2 = __shfl_sync(FULLM, e2, srcA);
        float y3 = __shfl_sync(FULLM, e3, srcA);
        float u0 = __shfl_sync(FULLM, e0, srcB);
        float u1 = __shfl_sync(FULLM, e1, srcB);
        float w2 = __shfl_sync(FULLM, e2, srcB);
        float w3 = __shfl_sync(FULLM, e3, srcB);

        unsigned pa0 = __float_as_uint(odd ? x1 : x0);
        unsigned pa1 = __float_as_uint(odd ? y3 : y2);
        unsigned pa2 = __float_as_uint(odd ? u1 : u0);
        unsigned pa3 = __float_as_uint(odd ? w3 : w2);

        asm volatile(
            "mma.sync.aligned.m16n8k8.row.col.f32.tf32.tf32.f32 "
            "{%0,%1,%2,%3}, {%4,%5,%6,%7}, {%8,%9}, {%0,%1,%2,%3};\n"
            : "+f"(o0), "+f"(o1), "+f"(o2), "+f"(o3)
            : "r"(pa0), "r"(pa1), "r"(pa2), "r"(pa3),
              "r"(vb0), "r"(vb1));
    }

    // l (row sums) live at n=5 -> col 2t+1 with t=2: regs o1 (row g), o3 (row g+8)
    unsigned lsrc = (lane & ~3u) | 2u;
    float l_lo = __shfl_sync(FULLM, o1, lsrc);
    float l_hi = __shfl_sync(FULLM, o3, lsrc);
    float inv_lo = 1.0f / l_lo;
    float inv_hi = 1.0f / l_hi;

    int g = lane >> 2;
    int q_lo = qt * 16 + g;
    int q_hi = q_lo + 8;
    int c0 = 2 * t, c1 = 2 * t + 1;
    if (c0 < NDK) {
        g_O[pair][b][q_lo][h * NDK + c0] = o0 * inv_lo;
        g_O[pair][b][q_hi][h * NDK + c0] = o2 * inv_hi;
    }
    if (c1 < NDK) {
        g_O[pair][b][q_lo][h * NDK + c1] = o1 * inv_lo;
        g_O[pair][b][q_hi][h * NDK + c1] = o3 * inv_hi;
    }
}

// ---------------------------------------------------------------------------
// 5) Sum 6 pair outputs + output projection W3/b3
// ---------------------------------------------------------------------------
__global__ void outproj_kernel(const float* __restrict__ W3,
                               const float* __restrict__ b3,
                               float* __restrict__ out) {
    __shared__ float sW[ND * ND];
    __shared__ float sb[ND];
    for (int i = threadIdx.x; i < ND * ND; i += blockDim.x) sW[i] = W3[i];
    for (int i = threadIdx.x; i < ND; i += blockDim.x) sb[i] = b3[i];
    __syncthreads();

    int bs = blockIdx.x * blockDim.x + threadIdx.x;
    if (bs >= NB * NS) return;

    const float* Ob = &g_O[0][0][0][0];
    float x[ND];
#pragma unroll
    for (int i = 0; i < ND; i++) {
        float tacc = 0.f;
#pragma unroll
        for (int p = 0; p < 6; p++)
            tacc += Ob[((size_t)p * NB * NS + bs) * ND + i];
        x[i] = tacc;
    }
    float* op = out + (size_t)bs * ND;
#pragma unroll
    for (int o = 0; o < ND; o++) {
        float y = sb[o];
#pragma unroll
        for (int i = 0; i < ND; i++) y = fmaf(x[i], sW[o * ND + i], y);
        op[o] = y;
    }
}

// ---------------------------------------------------------------------------
extern "C" void kernel_launch(void* const* d_in, const int* in_sizes, int n_in,
                              void* d_out, int out_size) {
    const float* q   = (const float*)d_in[0];
    const float* k   = (const float*)d_in[1];
    const float* v   = (const float*)d_in[2];
    const int*   msk = (const int*)d_in[3];
    const float* W0  = (const float*)d_in[4];
    const float* b0  = (const float*)d_in[5];
    const float* W1  = (const float*)d_in[6];
    const float* b1  = (const float*)d_in[7];
    const float* W2  = (const float*)d_in[8];
    const float* b2  = (const float*)d_in[9];
    const float* W3  = (const float*)d_in[10];
    const float* b3  = (const float*)d_in[11];
    float* out = (float*)d_out;

    compact_kernel<<<NB, 32>>>(msk);
    zero_kernel<<<1024, 256>>>();
    ones_kernel<<<(3 * NB * NH * 256 * 8 + 255) / 256, 256>>>();
    proj_kernel<<<(3 * NB * NS + 255) / 256, 256>>>(q, k, v, W0, b0, W1, b1, W2, b2);
    attn_kernel<<<6 * 1024, 128>>>();
    outproj_kernel<<<(NB * NS + 127) / 128, 128>>>(W3, b3, out);
}

// round 4
// speedup vs baseline: 2.4660x; 1.9055x over previous
#include <cuda_runtime.h>

#define NB 8
#define NS 2048
#define ND 20
#define NH 4
#define NDK 5
#define FULLM 0xffffffffu

__device__ __forceinline__ float ex2f(float x) {
    float r; asm("ex2.approx.ftz.f32 %0, %1;" : "=f"(r) : "f"(x)); return r;
}
__device__ __forceinline__ float tf32r(float x) {
    unsigned u; asm("cvt.rna.tf32.f32 %0, %1;" : "=r"(u) : "f"(x));
    return __uint_as_float(u);
}

// Scratch (device globals)
__device__ int   g_cidx[NB][NS];
__device__ int   g_nk[NB];
// mma.m16n8k8 fragment planes:
// Qf: A-frag of QK mma (16q x 8dims, dims padded 5->8)
// Kf: B-frag of QK mma (8dims x 8keys), key slot = compact index (identity)
// Vf: B-frag of PV mma (8keys x 8dims); key rows permuted by M=[0,2,4,6,1,3,5,7]
//     so that S C-frag feeds PV A-frag with NO shuffles; n=5 is the ones col.
__device__ float g_Qf[3][NB][NH][128][4][32];
__device__ float g_Kf[3][NB][NH][256][2][32];
__device__ float g_Vf[3][NB][NH][256][2][32];
__device__ float g_O[NB][NS][ND];   // summed over all 6 pairs

// ---------------------------------------------------------------------------
// 1) Per-batch key compaction
// ---------------------------------------------------------------------------
__global__ void compact_kernel(const int* __restrict__ mask) {
    int b = blockIdx.x;
    int lane = threadIdx.x;
    int count = 0;
    for (int s0 = 0; s0 < NS; s0 += 32) {
        int m = mask[b * NS + s0 + lane];
        unsigned bal = __ballot_sync(FULLM, m != 0);
        int pos = count + __popc(bal & ((1u << lane) - 1u));
        g_cidx[b][s0 + lane] = m ? pos : -1;
        count += __popc(bal);
    }
    if (lane == 0) g_nk[b] = count;
}

// ---------------------------------------------------------------------------
// 2a) Zero fragment arrays (pads must be 0)
// ---------------------------------------------------------------------------
__global__ void zero_kernel() {
    size_t nq = sizeof(g_Qf) / 16, nk = sizeof(g_Kf) / 16, nv = sizeof(g_Vf) / 16;
    size_t n4 = nq + nk + nv;
    float4 z = make_float4(0.f, 0.f, 0.f, 0.f);
    float4* q  = reinterpret_cast<float4*>(&g_Qf[0][0][0][0][0][0]);
    float4* kp = reinterpret_cast<float4*>(&g_Kf[0][0][0][0][0][0]);
    float4* vp = reinterpret_cast<float4*>(&g_Vf[0][0][0][0][0][0]);
    for (size_t i = blockIdx.x * blockDim.x + threadIdx.x; i < n4;
         i += (size_t)gridDim.x * blockDim.x) {
        if (i < nq) q[i] = z;
        else if (i < nq + nk) kp[i - nq] = z;
        else vp[i - nq - nk] = z;
    }
}

// 2b) Ones column (n=5) of V fragments for valid keys (permuted layout)
__global__ void ones_kernel() {
    int idx = blockIdx.x * blockDim.x + threadIdx.x;
    if (idx >= 3 * NB * NH * 256 * 8) return;
    int w   = idx & 7;
    int ch  = (idx >> 3) & 255;
    int h   = (idx >> 11) & 3;
    int b   = (idx >> 13) & 7;
    int src = idx >> 16;
    if (ch * 8 + w < g_nk[b]) {
        // logical key w -> k2 slot: plane = w&1, r = w>>1 ; lane = n*4+r, n=5
        g_Vf[src][b][h][ch][w & 1][20 + (w >> 1)] = 1.0f;
    }
}

// ---------------------------------------------------------------------------
// 3) All 9 projections -> fragment layouts (Q prescaled by log2e/sqrt(5))
// ---------------------------------------------------------------------------
__global__ void proj_kernel(const float* __restrict__ xq,
                            const float* __restrict__ xk,
                            const float* __restrict__ xv,
                            const float* __restrict__ W0, const float* __restrict__ b0,
                            const float* __restrict__ W1, const float* __restrict__ b1,
                            const float* __restrict__ W2, const float* __restrict__ b2) {
    __shared__ float sW[3][ND * ND];
    __shared__ float sb[3][ND];
    for (int i = threadIdx.x; i < ND * ND; i += blockDim.x) {
        sW[0][i] = W0[i]; sW[1][i] = W1[i]; sW[2][i] = W2[i];
    }
    for (int i = threadIdx.x; i < ND; i += blockDim.x) {
        sb[0][i] = b0[i]; sb[1][i] = b1[i]; sb[2][i] = b2[i];
    }
    __syncthreads();

    int idx = blockIdx.x * blockDim.x + threadIdx.x;
    if (idx >= 3 * NB * NS) return;
    int src = idx / (NB * NS);
    int bs  = idx - src * (NB * NS);
    int b   = bs / NS;
    int s   = bs - b * NS;

    const float* x = (src == 0 ? xq : (src == 1 ? xk : xv)) + (size_t)bs * ND;
    float xr[ND];
#pragma unroll
    for (int i = 0; i < ND; i++) xr[i] = x[i];

    int cj = g_cidx[b][s];
    int qt = s >> 4, r = s & 15;
    int qg = r & 7, half = r >> 3;
    int ch = cj >> 3;
    int w  = cj & 7;                 // within-chunk slot
    int vplane = w & 1, vr = w >> 1; // V permuted mapping
    const float qsc = 1.44269504088896340736f * 0.44721359549995793928f;

#pragma unroll
    for (int o = 0; o < ND; o++) {
        float y0 = sb[0][o], y1 = sb[1][o], y2 = sb[2][o];
#pragma unroll
        for (int i = 0; i < ND; i++) {
            y0 = fmaf(xr[i], sW[0][o * ND + i], y0);
            y1 = fmaf(xr[i], sW[1][o * ND + i], y1);
            y2 = fmaf(xr[i], sW[2][o * ND + i], y2);
        }
        int h = o / NDK, d = o - h * NDK;
        y0 = tf32r(y0 * qsc);
        y1 = tf32r(y1);
        y2 = tf32r(y2);
        if (d < 4) g_Qf[src][b][h][qt][half][qg * 4 + d] = y0;
        else       g_Qf[src][b][h][qt][2 + half][qg * 4] = y0;
        if (cj >= 0) {
            if (d < 4) g_Kf[src][b][h][ch][0][w * 4 + d] = y1;
            else       g_Kf[src][b][h][ch][1][w * 4] = y1;
            g_Vf[src][b][h][ch][vplane][d * 4 + vr] = y2;
        }
    }
}

// ---------------------------------------------------------------------------
// 4) Attention: warp = (b,h,16q), loops 8-key chunks; all 6 pairs fused.
//    Score C-frag -> EX2 in place -> PV A-frag directly (V key-permuted).
// ---------------------------------------------------------------------------
#define SMMA(s0, s1, s2, s3, A, B0, B1)                                      \
    asm volatile(                                                            \
        "mma.sync.aligned.m16n8k8.row.col.f32.tf32.tf32.f32 "                \
        "{%0,%1,%2,%3}, {%4,%5,%6,%7}, {%8,%9}, {%10,%10,%10,%10};\n"        \
        : "=f"(s0), "=f"(s1), "=f"(s2), "=f"(s3)                             \
        : "r"(A[0]), "r"(A[1]), "r"(A[2]), "r"(A[3]),                        \
          "r"(B0), "r"(B1), "f"(0.f))

#define PVMMA(O, e0, e1, e2, e3, B0, B1)                                     \
    asm volatile(                                                            \
        "mma.sync.aligned.m16n8k8.row.col.f32.tf32.tf32.f32 "                \
        "{%0,%1,%2,%3}, {%4,%5,%6,%7}, {%8,%9}, {%0,%1,%2,%3};\n"            \
        : "+f"(O[0]), "+f"(O[1]), "+f"(O[2]), "+f"(O[3])                     \
        : "r"(__float_as_uint(e0)), "r"(__float_as_uint(e2)),                \
          "r"(__float_as_uint(e1)), "r"(__float_as_uint(e3)),                \
          "r"(B0), "r"(B1))

#define DO_PAIR(P, A)                                                        \
    {                                                                        \
        float s0, s1, s2, s3;                                                \
        SMMA(s0, s1, s2, s3, ua[A], kb0, kb1);                               \
        float e0 = ex2f(s0), e1 = ex2f(s1), e2 = ex2f(s2), e3 = ex2f(s3);    \
        PVMMA(o[P], e0, e1, e2, e3, vb0, vb1);                               \
    }

__global__ void __launch_bounds__(128) attn_kernel() {
    int bi  = blockIdx.x;                 // [NB][NH][32]
    int b   = bi >> 7;
    int h   = (bi >> 5) & 3;
    int qt4 = bi & 31;
    int wid  = threadIdx.x >> 5;
    int lane = threadIdx.x & 31;
    int qt   = qt4 * 4 + wid;
    int nc = (g_nk[b] + 7) >> 3;

    unsigned ua[3][4];
#pragma unroll
    for (int a = 0; a < 3; a++) {
        const float* Qb = &g_Qf[a][b][h][qt][0][0];
#pragma unroll
        for (int p = 0; p < 4; p++) ua[a][p] = __float_as_uint(Qb[p * 32 + lane]);
    }
    const float* K0 = &g_Kf[0][b][h][0][0][0];
    const float* K1 = &g_Kf[1][b][h][0][0][0];
    const float* K2 = &g_Kf[2][b][h][0][0][0];
    const float* V0 = &g_Vf[0][b][h][0][0][0];
    const float* V1 = &g_Vf[1][b][h][0][0][0];
    const float* V2 = &g_Vf[2][b][h][0][0][0];

    float o[6][4];
#pragma unroll
    for (int p = 0; p < 6; p++)
#pragma unroll
        for (int i = 0; i < 4; i++) o[p][i] = 0.f;

    for (int ch = 0; ch < nc; ch++) {
        int off = ch * 64 + lane;
        {   // c = 0 : pairs 1 (a=1), 3 (a=2)
            unsigned kb0 = __float_as_uint(K0[off]);
            unsigned kb1 = __float_as_uint(K0[off + 32]);
            unsigned vb0 = __float_as_uint(V0[off]);
            unsigned vb1 = __float_as_uint(V0[off + 32]);
            DO_PAIR(1, 1);
            DO_PAIR(3, 2);
        }
        {   // c = 1 : pairs 0 (a=0), 5 (a=2)
            unsigned kb0 = __float_as_uint(K1[off]);
            unsigned kb1 = __float_as_uint(K1[off + 32]);
            unsigned vb0 = __float_as_uint(V1[off]);
            unsigned vb1 = __float_as_uint(V1[off + 32]);
            DO_PAIR(0, 0);
            DO_PAIR(5, 2);
        }
        {   // c = 2 : pairs 2 (a=0), 4 (a=1)
            unsigned kb0 = __float_as_uint(K2[off]);
            unsigned kb1 = __float_as_uint(K2[off + 32]);
            unsigned vb0 = __float_as_uint(V2[off]);
            unsigned vb1 = __float_as_uint(V2[off + 32]);
            DO_PAIR(2, 0);
            DO_PAIR(4, 1);
        }
    }

    // Normalize each pair (l lives at col 5 = reg1/reg3 of lane group t=2), sum.
    int t = lane & 3;
    int g = lane >> 2;
    unsigned lsrc = (lane & ~3u) | 2u;
    float r0 = 0.f, r1 = 0.f, r2 = 0.f, r3 = 0.f;
#pragma unroll
    for (int p = 0; p < 6; p++) {
        float llo = __shfl_sync(FULLM, o[p][1], lsrc);
        float lhi = __shfl_sync(FULLM, o[p][3], lsrc);
        float ilo = 1.0f / llo;
        float ihi = 1.0f / lhi;
        r0 = fmaf(o[p][0], ilo, r0);
        r1 = fmaf(o[p][1], ilo, r1);
        r2 = fmaf(o[p][2], ihi, r2);
        r3 = fmaf(o[p][3], ihi, r3);
    }

    int q_lo = qt * 16 + g;
    int q_hi = q_lo + 8;
    int c0 = 2 * t;
    if (c0 < 4) {
        g_O[b][q_lo][h * NDK + c0]     = r0;
        g_O[b][q_lo][h * NDK + c0 + 1] = r1;
        g_O[b][q_hi][h * NDK + c0]     = r2;
        g_O[b][q_hi][h * NDK + c0 + 1] = r3;
    } else if (c0 == 4) {
        g_O[b][q_lo][h * NDK + 4] = r0;
        g_O[b][q_hi][h * NDK + 4] = r2;
    }
}

// ---------------------------------------------------------------------------
// 5) Output projection W3/b3 (inputs already summed over pairs)
// ---------------------------------------------------------------------------
__global__ void outproj_kernel(const float* __restrict__ W3,
                               const float* __restrict__ b3,
                               float* __restrict__ out) {
    __shared__ float sW[ND * ND];
    __shared__ float sb[ND];
    for (int i = threadIdx.x; i < ND * ND; i += blockDim.x) sW[i] = W3[i];
    for (int i = threadIdx.x; i < ND; i += blockDim.x) sb[i] = b3[i];
    __syncthreads();

    int bs = blockIdx.x * blockDim.x + threadIdx.x;
    if (bs >= NB * NS) return;

    const float* xp = &g_O[0][0][0] + (size_t)bs * ND;
    float x[ND];
#pragma unroll
    for (int i = 0; i < ND; i++) x[i] = xp[i];
    float* op = out + (size_t)bs * ND;
#pragma unroll
    for (int o = 0; o < ND; o++) {
        float y = sb[o];
#pragma unroll
        for (int i = 0; i < ND; i++) y = fmaf(x[i], sW[o * ND + i], y);
        op[o] = y;
    }
}

// ---------------------------------------------------------------------------
extern "C" void kernel_launch(void* const* d_in, const int* in_sizes, int n_in,
                              void* d_out, int out_size) {
    const float* q   = (const float*)d_in[0];
    const float* k   = (const float*)d_in[1];
    const float* v   = (const float*)d_in[2];
    const int*   msk = (const int*)d_in[3];
    const float* W0  = (const float*)d_in[4];
    const float* b0  = (const float*)d_in[5];
    const float* W1  = (const float*)d_in[6];
    const float* b1  = (const float*)d_in[7];
    const float* W2  = (const float*)d_in[8];
    const float* b2  = (const float*)d_in[9];
    const float* W3  = (const float*)d_in[10];
    const float* b3  = (const float*)d_in[11];
    float* out = (float*)d_out;

    compact_kernel<<<NB, 32>>>(msk);
    zero_kernel<<<1024, 256>>>();
    ones_kernel<<<(3 * NB * NH * 256 * 8 + 255) / 256, 256>>>();
    proj_kernel<<<(3 * NB * NS + 255) / 256, 256>>>(q, k, v, W0, b0, W1, b1, W2, b2);
    attn_kernel<<<NB * NH * 32, 128>>>();
    outproj_kernel<<<(NB * NS + 127) / 128, 128>>>(W3, b3, out);
}